// round 5
// baseline (speedup 1.0000x reference)
#include <cuda_runtime.h>

typedef unsigned long long U64;

// ---------------- static device scratch ----------------
__device__ float g_xp[16777216];   // [2][64][1024][128] gate pre-activations
__device__ float g_h0[4194304];    // [64][1024][64]
__device__ float g_h1[4194304];    // [64][1024][64]
__device__ float g_part1[4194304]; // [32][64][2048] fc1 split-K partials
__device__ float g_hidden[131072]; // [64][2048]
__device__ float g_part2[2359296]; // [4][64][9216] fc2 split-K partials

// ---------------- helpers ----------------
__device__ __forceinline__ void ffma2(U64 &acc, U64 a, U64 b){
    asm("fma.rn.f32x2 %0, %1, %2, %0;" : "+l"(acc) : "l"(a), "l"(b));
}
__device__ __forceinline__ U64 add2(U64 a, U64 b){
    U64 r; asm("add.rn.f32x2 %0, %1, %2;" : "=l"(r) : "l"(a), "l"(b)); return r;
}
__device__ __forceinline__ float2 unpk(U64 v){
    float2 r; asm("mov.b64 {%0, %1}, %2;" : "=f"(r.x), "=f"(r.y) : "l"(v)); return r;
}
__device__ __forceinline__ float sum2(U64 v){ float2 r = unpk(v); return r.x + r.y; }
__device__ __forceinline__ float fex2(float x){ float r; asm("ex2.approx.ftz.f32 %0, %1;" : "=f"(r) : "f"(x)); return r; }
__device__ __forceinline__ float frcp(float x){ float r; asm("rcp.approx.ftz.f32 %0, %1;" : "=f"(r) : "f"(x)); return r; }
__device__ __forceinline__ float sigf (float x){ return frcp(1.0f + fex2(-1.4426950408889634f * x)); }
__device__ __forceinline__ float tanhx(float x){ return fmaf(-2.0f, frcp(1.0f + fex2(2.8853900817779268f * x)), 1.0f); }

// ---------------- xproj layer 0 (K=9) ----------------
__global__ void xproj0_kernel(const float* __restrict__ x,
    const float* __restrict__ wf, const float* __restrict__ bif, const float* __restrict__ bhf,
    const float* __restrict__ wr, const float* __restrict__ bir, const float* __restrict__ bhr)
{
    int idx = blockIdx.x * 256 + threadIdx.x;
    int j = idx & 127;
    int s = (idx >> 7) & 1023;
    int b = (idx >> 17) & 63;
    int d = idx >> 23;
    const float* w = d ? wr : wf;
    float acc = d ? (bir[j] + bhr[j]) : (bif[j] + bhf[j]);
    int tsrc = d ? (1023 - s) : s;
    const float* xr = x + ((size_t)b * 1024 + tsrc) * 9;
    const float* wrow = w + j * 9;
    #pragma unroll
    for (int k = 0; k < 9; k++) acc = fmaf(xr[k], wrow[k], acc);
    g_xp[idx] = acc;
}

// ---------------- xproj layer 1 (K=64, f32x2) ----------------
__global__ void xproj1_kernel(
    const float* __restrict__ wf, const float* __restrict__ bif, const float* __restrict__ bhf,
    const float* __restrict__ wr, const float* __restrict__ bir, const float* __restrict__ bhr)
{
    int idx = blockIdx.x * 256 + threadIdx.x;
    int j = idx & 127;
    int s = (idx >> 7) & 1023;
    int b = (idx >> 17) & 63;
    int d = idx >> 23;
    const float* w = d ? wr : wf;
    float bias = d ? (bir[j] + bhr[j]) : (bif[j] + bhf[j]);
    int tsrc = d ? (1023 - s) : s;
    const ulonglong2* hp = (const ulonglong2*)(g_h0 + ((size_t)b * 1024 + tsrc) * 64);
    const ulonglong2* wp = (const ulonglong2*)(w + j * 64);
    U64 acc = 0ull;
    #pragma unroll
    for (int r = 0; r < 16; r++){
        ulonglong2 hv = hp[r];
        ulonglong2 wv = wp[r];
        ffma2(acc, hv.x, wv.x);
        ffma2(acc, hv.y, wv.y);
    }
    g_xp[idx] = bias + sum2(acc);
}

// ---------------- LSTM recurrence: 4 warps (one per gate) per (dir, batch) ----------------
__global__ void __launch_bounds__(128, 1) lstm_kernel(
    const float* __restrict__ whh_f, const float* __restrict__ whh_r, int outsel)
{
    const int blk = blockIdx.x;          // 0..127
    const int d = blk >> 6, b = blk & 63;
    const int tid = threadIdx.x;
    const int g = tid >> 5;              // gate 0..3 (i,f,g,o)
    const int hh = tid & 31;             // hidden unit
    float* hout = outsel ? g_h1 : g_h0;
    const float* whh = d ? whh_r : whh_f;

    // this lane's Whh row (gate g, unit hh): 32 floats as 16 f32x2 pairs in registers
    U64 wp[16];
    {
        const ulonglong2* wr2 = (const ulonglong2*)(whh + (g * 32 + hh) * 32);
        #pragma unroll
        for (int r = 0; r < 8; r++){ ulonglong2 v = wr2[r]; wp[2*r] = v.x; wp[2*r+1] = v.y; }
    }

    __shared__ __align__(16) float hs[32];
    __shared__ __align__(16) float gbuf[96];   // activated gates i,f,g: [gate][hh]
    if (tid < 32) hs[tid] = 0.0f;
    float c = 0.0f;                            // live only on warp 3 lanes
    __syncthreads();

    const float* xq = g_xp + (size_t)(d * 64 + b) * 1024 * 128 + g * 32 + hh;
    float cur = xq[0];
    float nxt = xq[128];

    float* outp = hout + (size_t)b * 1024 * 64 + d * 32 + hh;

    for (int s = 0; s < 1024; s++){
        float nn = 0.0f;
        if (s + 2 < 1024) nn = xq[(size_t)(s + 2) * 128];

        // gate pre-activation: dot(whh_row, h) + xp   (two 8-deep FFMA2 chains)
        U64 a0 = 0ull, a1 = 0ull;
        const ulonglong2* h2 = (const ulonglong2*)hs;   // warp-broadcast loads
        #pragma unroll
        for (int r = 0; r < 8; r++){
            ulonglong2 hv = h2[r];
            ffma2(a0, hv.x, wp[2*r]);
            ffma2(a1, hv.y, wp[2*r+1]);
        }
        float pre = cur + sum2(add2(a0, a1));
        float act = (g == 2) ? tanhx(pre) : sigf(pre);
        if (g < 3) gbuf[g * 32 + hh] = act;
        __syncthreads();                      // gates visible to warp 3; hs reads done

        if (g == 3){
            float iv = gbuf[hh];
            float fv = gbuf[32 + hh];
            float gv = gbuf[64 + hh];
            c = fmaf(fv, c, iv * gv);
            float hval = act * tanhx(c);
            hs[hh] = hval;
            int tout = d ? (1023 - s) : s;
            outp[(size_t)tout * 64] = hval;
        }
        __syncthreads();                      // new h visible before next step

        cur = nxt; nxt = nn;
    }
}

// ---------------- conflict-free f32x2 GEMM w/ split-K ----------------
// part[split][64][N] = X[64][K] @ W[N][K]^T ; block tile 64b x 128n, 256 threads.
#define FCW 132   // padded row stride (floats); 528B: 16B-aligned rows

__global__ void __launch_bounds__(256) fc_kernel(
    const float* __restrict__ W, int sel, int N, int K, int kPerSplit)
{
    const float* __restrict__ X = sel ? g_hidden : g_h1;
    float* __restrict__ part = sel ? g_part2 : g_part1;

    __shared__ float ws[32 * FCW];   // [k][n] 0..127
    __shared__ float fs[32 * FCW];   // [k][2b duplicated]

    const int tid = threadIdx.x;
    const int nq = tid & 15;         // n slices [nq*4,+4) and [64+nq*4,+4)
    const int bq = tid >> 4;         // b group of 4: [bq*4,+4)
    const int mbase = blockIdx.x * 128;
    const int kstart = blockIdx.y * kPerSplit;

    // staging maps
    const int sn  = tid & 127;       // W: row n
    const int skq = tid >> 7;        // W: k-half (16 k each)
    const int xb_ = tid & 63;        // X: row b
    const int xkq = tid >> 6;        // X: k-quarter (8 k each)

    U64 acc[4][4];
    #pragma unroll
    for (int i = 0; i < 4; i++)
        #pragma unroll
        for (int j = 0; j < 4; j++) acc[i][j] = 0ull;

    const int nchunk = kPerSplit / 32;
    for (int ch = 0; ch < nchunk; ch++){
        int k0 = kstart + ch * 32;

        // ---- stage W tile: ws[k][n] = W[mbase+n][k0+k] ----
        {
            const float4* src = (const float4*)(W + (size_t)(mbase + sn) * K + k0 + skq * 16);
            float4 v0 = src[0], v1 = src[1], v2 = src[2], v3 = src[3];
            int kb = skq * 16;
            ws[(kb+ 0)*FCW + sn] = v0.x; ws[(kb+ 1)*FCW + sn] = v0.y;
            ws[(kb+ 2)*FCW + sn] = v0.z; ws[(kb+ 3)*FCW + sn] = v0.w;
            ws[(kb+ 4)*FCW + sn] = v1.x; ws[(kb+ 5)*FCW + sn] = v1.y;
            ws[(kb+ 6)*FCW + sn] = v1.z; ws[(kb+ 7)*FCW + sn] = v1.w;
            ws[(kb+ 8)*FCW + sn] = v2.x; ws[(kb+ 9)*FCW + sn] = v2.y;
            ws[(kb+10)*FCW + sn] = v2.z; ws[(kb+11)*FCW + sn] = v2.w;
            ws[(kb+12)*FCW + sn] = v3.x; ws[(kb+13)*FCW + sn] = v3.y;
            ws[(kb+14)*FCW + sn] = v3.z; ws[(kb+15)*FCW + sn] = v3.w;
        }
        // ---- stage X tile duplicated: fs[k][2b]=fs[k][2b+1]=X[b][k0+k] ----
        {
            const float4* src = (const float4*)(X + (size_t)xb_ * K + k0 + xkq * 8);
            float4 u0 = src[0], u1 = src[1];
            int kb = xkq * 8;
            *(float2*)&fs[(kb+0)*FCW + 2*xb_] = make_float2(u0.x, u0.x);
            *(float2*)&fs[(kb+1)*FCW + 2*xb_] = make_float2(u0.y, u0.y);
            *(float2*)&fs[(kb+2)*FCW + 2*xb_] = make_float2(u0.z, u0.z);
            *(float2*)&fs[(kb+3)*FCW + 2*xb_] = make_float2(u0.w, u0.w);
            *(float2*)&fs[(kb+4)*FCW + 2*xb_] = make_float2(u1.x, u1.x);
            *(float2*)&fs[(kb+5)*FCW + 2*xb_] = make_float2(u1.y, u1.y);
            *(float2*)&fs[(kb+6)*FCW + 2*xb_] = make_float2(u1.z, u1.z);
            *(float2*)&fs[(kb+7)*FCW + 2*xb_] = make_float2(u1.w, u1.w);
        }
        __syncthreads();

        #pragma unroll
        for (int kk = 0; kk < 32; kk++){
            ulonglong2 wa = *(const ulonglong2*)&ws[kk*FCW + nq*4];        // n pairs (0,1),(2,3)
            ulonglong2 wb = *(const ulonglong2*)&ws[kk*FCW + 64 + nq*4];   // +64 half
            ulonglong2 xa = *(const ulonglong2*)&fs[kk*FCW + bq*8];        // dup(b0),dup(b1)
            ulonglong2 xc = *(const ulonglong2*)&fs[kk*FCW + bq*8 + 4];    // dup(b2),dup(b3)
            U64 xv0 = xa.x, xv1 = xa.y, xv2 = xc.x, xv3 = xc.y;
            ffma2(acc[0][0], xv0, wa.x); ffma2(acc[0][1], xv0, wa.y);
            ffma2(acc[0][2], xv0, wb.x); ffma2(acc[0][3], xv0, wb.y);
            ffma2(acc[1][0], xv1, wa.x); ffma2(acc[1][1], xv1, wa.y);
            ffma2(acc[1][2], xv1, wb.x); ffma2(acc[1][3], xv1, wb.y);
            ffma2(acc[2][0], xv2, wa.x); ffma2(acc[2][1], xv2, wa.y);
            ffma2(acc[2][2], xv2, wb.x); ffma2(acc[2][3], xv2, wb.y);
            ffma2(acc[3][0], xv3, wa.x); ffma2(acc[3][1], xv3, wa.y);
            ffma2(acc[3][2], xv3, wb.x); ffma2(acc[3][3], xv3, wb.y);
        }
        __syncthreads();
    }

    #pragma unroll
    for (int b4 = 0; b4 < 4; b4++){
        int b = bq * 4 + b4;
        float* dst = part + ((size_t)blockIdx.y * 64 + b) * N + mbase;
        *(float2*)(dst + nq*4)          = unpk(acc[b4][0]);
        *(float2*)(dst + nq*4 + 2)      = unpk(acc[b4][1]);
        *(float2*)(dst + 64 + nq*4)     = unpk(acc[b4][2]);
        *(float2*)(dst + 64 + nq*4 + 2) = unpk(acc[b4][3]);
    }
}

// ---------------- split-K reductions ----------------
__global__ void reduce1_kernel(const float* __restrict__ bias){
    int i = blockIdx.x * 256 + threadIdx.x;   // 131072
    int m = i & 2047, b = i >> 11;
    float acc = bias[m];
    #pragma unroll
    for (int s = 0; s < 32; s++) acc += g_part1[((size_t)s * 64 + b) * 2048 + m];
    g_hidden[i] = fmaxf(acc, 0.0f);
}

__global__ void reduce2_kernel(const float* __restrict__ bias, float* __restrict__ out){
    int i = blockIdx.x * 256 + threadIdx.x;   // 589824
    int n = i % 9216, b = i / 9216;
    float acc = bias[n];
    #pragma unroll
    for (int s = 0; s < 4; s++) acc += g_part2[((size_t)s * 64 + b) * 9216 + n];
    out[i] = acc;
}

// ---------------- launcher ----------------
extern "C" void kernel_launch(void* const* d_in, const int* in_sizes, int n_in,
                              void* d_out, int out_size)
{
    const float* x     = (const float*)d_in[0];
    const float* wih0  = (const float*)d_in[1];
    const float* whh0  = (const float*)d_in[2];
    const float* bih0  = (const float*)d_in[3];
    const float* bhh0  = (const float*)d_in[4];
    const float* wih0r = (const float*)d_in[5];
    const float* whh0r = (const float*)d_in[6];
    const float* bih0r = (const float*)d_in[7];
    const float* bhh0r = (const float*)d_in[8];
    const float* wih1  = (const float*)d_in[9];
    const float* whh1  = (const float*)d_in[10];
    const float* bih1  = (const float*)d_in[11];
    const float* bhh1  = (const float*)d_in[12];
    const float* wih1r = (const float*)d_in[13];
    const float* whh1r = (const float*)d_in[14];
    const float* bih1r = (const float*)d_in[15];
    const float* bhh1r = (const float*)d_in[16];
    const float* fc1w  = (const float*)d_in[17];
    const float* fc1b  = (const float*)d_in[18];
    const float* fc2w  = (const float*)d_in[19];
    const float* fc2b  = (const float*)d_in[20];
    float* out = (float*)d_out;

    xproj0_kernel<<<65536, 256>>>(x, wih0, bih0, bhh0, wih0r, bih0r, bhh0r);
    lstm_kernel<<<128, 128>>>(whh0, whh0r, 0);
    xproj1_kernel<<<65536, 256>>>(wih1, bih1, bhh1, wih1r, bih1r, bhh1r);
    lstm_kernel<<<128, 128>>>(whh1, whh1r, 1);

    // fc1: N=2048, K=65536, split-K=32 (kPerSplit=2048) -> grid (16, 32)
    fc_kernel<<<dim3(16, 32), 256>>>(fc1w, 0, 2048, 65536, 2048);
    reduce1_kernel<<<512, 256>>>(fc1b);

    // fc2: N=9216, K=2048, split-K=4 (kPerSplit=512) -> grid (72, 4)
    fc_kernel<<<dim3(72, 4), 256>>>(fc2w, 1, 9216, 2048, 512);
    reduce2_kernel<<<2304, 256>>>(fc2b, out);
}

// round 6
// speedup vs baseline: 1.8016x; 1.8016x over previous
#include <cuda_runtime.h>

typedef unsigned long long U64;

// ---------------- static device scratch ----------------
__device__ float g_xp[16777216];   // [2][64][1024][128] gate pre-activations
__device__ float g_h0[4194304];    // [64][1024][64]
__device__ float g_h1[4194304];    // [64][1024][64]
__device__ float g_part1[4194304]; // [32][64][2048] fc1 split-K partials
__device__ float g_hidden[131072]; // [64][2048]
__device__ float g_part2[2359296]; // [4][64][9216] fc2 split-K partials

// ---------------- helpers ----------------
__device__ __forceinline__ void ffma2(U64 &acc, U64 a, U64 b){
    asm("fma.rn.f32x2 %0, %1, %2, %0;" : "+l"(acc) : "l"(a), "l"(b));
}
__device__ __forceinline__ U64 add2(U64 a, U64 b){
    U64 r; asm("add.rn.f32x2 %0, %1, %2;" : "=l"(r) : "l"(a), "l"(b)); return r;
}
__device__ __forceinline__ float2 unpk(U64 v){
    float2 r; asm("mov.b64 {%0, %1}, %2;" : "=f"(r.x), "=f"(r.y) : "l"(v)); return r;
}
__device__ __forceinline__ float sum2(U64 v){ float2 r = unpk(v); return r.x + r.y; }
__device__ __forceinline__ float fex2(float x){ float r; asm("ex2.approx.ftz.f32 %0, %1;" : "=f"(r) : "f"(x)); return r; }
__device__ __forceinline__ float frcp(float x){ float r; asm("rcp.approx.ftz.f32 %0, %1;" : "=f"(r) : "f"(x)); return r; }
__device__ __forceinline__ float sigf (float x){ return frcp(1.0f + fex2(-1.4426950408889634f * x)); }
__device__ __forceinline__ float tanhx(float x){ return fmaf(-2.0f, frcp(1.0f + fex2(2.8853900817779268f * x)), 1.0f); }

#define TW 132   // padded smem row stride (floats)

// ---------------- xproj layer 0: tiled, K=9 ----------------
// grid (16 s-tiles, 64 b, 2 d); block 256; out tile 64 rows x 128 gates.
__global__ void __launch_bounds__(256) xproj0_kernel(const float* __restrict__ x,
    const float* __restrict__ wf, const float* __restrict__ bif, const float* __restrict__ bhf,
    const float* __restrict__ wr, const float* __restrict__ bir, const float* __restrict__ bhr)
{
    __shared__ float ws[9 * TW];   // [k][j]
    __shared__ float fs[9 * TW];   // [k][2r] duplicated
    const int tid = threadIdx.x;
    const int s0 = blockIdx.x * 64;
    const int b  = blockIdx.y;
    const int d  = blockIdx.z;
    const float* w  = d ? wr : wf;
    const float* bi = d ? bir : bif;
    const float* bh = d ? bhr : bhf;

    if (tid < 128){                       // stage W: row j = tid
        const float* src = w + tid * 9;
        #pragma unroll
        for (int k = 0; k < 9; k++) ws[k * TW + tid] = src[k];
    } else if (tid < 192){                // stage x tile: row r = tid-128
        int r = tid - 128;
        int s = s0 + r;
        int tsrc = d ? (1023 - s) : s;
        const float* src = x + ((size_t)b * 1024 + tsrc) * 9;
        #pragma unroll
        for (int k = 0; k < 9; k++){
            float v = src[k];
            *(float2*)&fs[k * TW + 2 * r] = make_float2(v, v);
        }
    }
    __syncthreads();

    const int nq = tid & 15;
    const int bq = tid >> 4;
    U64 acc[4][4];
    #pragma unroll
    for (int i = 0; i < 4; i++)
        #pragma unroll
        for (int j = 0; j < 4; j++) acc[i][j] = 0ull;

    #pragma unroll
    for (int kk = 0; kk < 9; kk++){
        ulonglong2 wa = *(const ulonglong2*)&ws[kk*TW + nq*4];
        ulonglong2 wb = *(const ulonglong2*)&ws[kk*TW + 64 + nq*4];
        ulonglong2 xa = *(const ulonglong2*)&fs[kk*TW + bq*8];
        ulonglong2 xc = *(const ulonglong2*)&fs[kk*TW + bq*8 + 4];
        U64 xv0 = xa.x, xv1 = xa.y, xv2 = xc.x, xv3 = xc.y;
        ffma2(acc[0][0], xv0, wa.x); ffma2(acc[0][1], xv0, wa.y);
        ffma2(acc[0][2], xv0, wb.x); ffma2(acc[0][3], xv0, wb.y);
        ffma2(acc[1][0], xv1, wa.x); ffma2(acc[1][1], xv1, wa.y);
        ffma2(acc[1][2], xv1, wb.x); ffma2(acc[1][3], xv1, wb.y);
        ffma2(acc[2][0], xv2, wa.x); ffma2(acc[2][1], xv2, wa.y);
        ffma2(acc[2][2], xv2, wb.x); ffma2(acc[2][3], xv2, wb.y);
        ffma2(acc[3][0], xv3, wa.x); ffma2(acc[3][1], xv3, wa.y);
        ffma2(acc[3][2], xv3, wb.x); ffma2(acc[3][3], xv3, wb.y);
    }

    // bias for this thread's 8 columns
    int j0 = nq * 4, j1 = 64 + nq * 4;
    float bv[8];
    #pragma unroll
    for (int q = 0; q < 4; q++){ bv[q] = bi[j0+q] + bh[j0+q]; bv[4+q] = bi[j1+q] + bh[j1+q]; }

    float* base = g_xp + ((size_t)(d * 64 + b) * 1024 + s0) * 128;
    #pragma unroll
    for (int b4 = 0; b4 < 4; b4++){
        float* dst = base + (size_t)(bq * 4 + b4) * 128;
        float2 v0 = unpk(acc[b4][0]); v0.x += bv[0]; v0.y += bv[1];
        float2 v1 = unpk(acc[b4][1]); v1.x += bv[2]; v1.y += bv[3];
        float2 v2 = unpk(acc[b4][2]); v2.x += bv[4]; v2.y += bv[5];
        float2 v3 = unpk(acc[b4][3]); v3.x += bv[6]; v3.y += bv[7];
        *(float2*)(dst + j0)     = v0;
        *(float2*)(dst + j0 + 2) = v1;
        *(float2*)(dst + j1)     = v2;
        *(float2*)(dst + j1 + 2) = v3;
    }
}

// ---------------- xproj layer 1: tiled GEMM, K=64 (two 32-k chunks) ----------------
__global__ void __launch_bounds__(256) xproj1_kernel(
    const float* __restrict__ wf, const float* __restrict__ bif, const float* __restrict__ bhf,
    const float* __restrict__ wr, const float* __restrict__ bir, const float* __restrict__ bhr)
{
    __shared__ float ws[32 * TW];
    __shared__ float fs[32 * TW];
    const int tid = threadIdx.x;
    const int s0 = blockIdx.x * 64;
    const int b  = blockIdx.y;
    const int d  = blockIdx.z;
    const float* w  = d ? wr : wf;
    const float* bi = d ? bir : bif;
    const float* bh = d ? bhr : bhf;

    const int sn  = tid & 127, skq = tid >> 7;   // W staging: row sn, k-half skq (16 k)
    const int xr  = tid & 63,  xkq = tid >> 6;   // X staging: row xr, k-quarter (8 k)
    int s = s0 + xr;
    int tsrc = d ? (1023 - s) : s;
    const float* wptr = w + sn * 64 + skq * 16;
    const float* hptr = g_h0 + ((size_t)b * 1024 + tsrc) * 64 + xkq * 8;

    const int nq = tid & 15;
    const int bq = tid >> 4;
    U64 acc[4][4];
    #pragma unroll
    for (int i = 0; i < 4; i++)
        #pragma unroll
        for (int j = 0; j < 4; j++) acc[i][j] = 0ull;

    #pragma unroll
    for (int ch = 0; ch < 2; ch++){
        if (ch){ __syncthreads(); }
        {   // stage W: 4 float4
            const float4* src = (const float4*)(wptr + ch * 32);
            float4 v0 = src[0], v1 = src[1], v2 = src[2], v3 = src[3];
            int kb = skq * 16;
            ws[(kb+ 0)*TW + sn] = v0.x; ws[(kb+ 1)*TW + sn] = v0.y;
            ws[(kb+ 2)*TW + sn] = v0.z; ws[(kb+ 3)*TW + sn] = v0.w;
            ws[(kb+ 4)*TW + sn] = v1.x; ws[(kb+ 5)*TW + sn] = v1.y;
            ws[(kb+ 6)*TW + sn] = v1.z; ws[(kb+ 7)*TW + sn] = v1.w;
            ws[(kb+ 8)*TW + sn] = v2.x; ws[(kb+ 9)*TW + sn] = v2.y;
            ws[(kb+10)*TW + sn] = v2.z; ws[(kb+11)*TW + sn] = v2.w;
            ws[(kb+12)*TW + sn] = v3.x; ws[(kb+13)*TW + sn] = v3.y;
            ws[(kb+14)*TW + sn] = v3.z; ws[(kb+15)*TW + sn] = v3.w;
        }
        {   // stage X duplicated: 2 float4
            const float4* src = (const float4*)(hptr + ch * 32);
            float4 u0 = src[0], u1 = src[1];
            int kb = xkq * 8;
            *(float2*)&fs[(kb+0)*TW + 2*xr] = make_float2(u0.x, u0.x);
            *(float2*)&fs[(kb+1)*TW + 2*xr] = make_float2(u0.y, u0.y);
            *(float2*)&fs[(kb+2)*TW + 2*xr] = make_float2(u0.z, u0.z);
            *(float2*)&fs[(kb+3)*TW + 2*xr] = make_float2(u0.w, u0.w);
            *(float2*)&fs[(kb+4)*TW + 2*xr] = make_float2(u1.x, u1.x);
            *(float2*)&fs[(kb+5)*TW + 2*xr] = make_float2(u1.y, u1.y);
            *(float2*)&fs[(kb+6)*TW + 2*xr] = make_float2(u1.z, u1.z);
            *(float2*)&fs[(kb+7)*TW + 2*xr] = make_float2(u1.w, u1.w);
        }
        __syncthreads();
        #pragma unroll
        for (int kk = 0; kk < 32; kk++){
            ulonglong2 wa = *(const ulonglong2*)&ws[kk*TW + nq*4];
            ulonglong2 wb = *(const ulonglong2*)&ws[kk*TW + 64 + nq*4];
            ulonglong2 xa = *(const ulonglong2*)&fs[kk*TW + bq*8];
            ulonglong2 xc = *(const ulonglong2*)&fs[kk*TW + bq*8 + 4];
            U64 xv0 = xa.x, xv1 = xa.y, xv2 = xc.x, xv3 = xc.y;
            ffma2(acc[0][0], xv0, wa.x); ffma2(acc[0][1], xv0, wa.y);
            ffma2(acc[0][2], xv0, wb.x); ffma2(acc[0][3], xv0, wb.y);
            ffma2(acc[1][0], xv1, wa.x); ffma2(acc[1][1], xv1, wa.y);
            ffma2(acc[1][2], xv1, wb.x); ffma2(acc[1][3], xv1, wb.y);
            ffma2(acc[2][0], xv2, wa.x); ffma2(acc[2][1], xv2, wa.y);
            ffma2(acc[2][2], xv2, wb.x); ffma2(acc[2][3], xv2, wb.y);
            ffma2(acc[3][0], xv3, wa.x); ffma2(acc[3][1], xv3, wa.y);
            ffma2(acc[3][2], xv3, wb.x); ffma2(acc[3][3], xv3, wb.y);
        }
    }

    int j0 = nq * 4, j1 = 64 + nq * 4;
    float bv[8];
    #pragma unroll
    for (int q = 0; q < 4; q++){ bv[q] = bi[j0+q] + bh[j0+q]; bv[4+q] = bi[j1+q] + bh[j1+q]; }

    float* base = g_xp + ((size_t)(d * 64 + b) * 1024 + s0) * 128;
    #pragma unroll
    for (int b4 = 0; b4 < 4; b4++){
        float* dst = base + (size_t)(bq * 4 + b4) * 128;
        float2 v0 = unpk(acc[b4][0]); v0.x += bv[0]; v0.y += bv[1];
        float2 v1 = unpk(acc[b4][1]); v1.x += bv[2]; v1.y += bv[3];
        float2 v2 = unpk(acc[b4][2]); v2.x += bv[4]; v2.y += bv[5];
        float2 v3 = unpk(acc[b4][3]); v3.x += bv[6]; v3.y += bv[7];
        *(float2*)(dst + j0)     = v0;
        *(float2*)(dst + j0 + 2) = v1;
        *(float2*)(dst + j1)     = v2;
        *(float2*)(dst + j1 + 2) = v3;
    }
}

// ---------------- LSTM recurrence: 4 warps (one per gate) per (dir, batch) ----------------
__global__ void __launch_bounds__(128, 1) lstm_kernel(
    const float* __restrict__ whh_f, const float* __restrict__ whh_r, int outsel)
{
    const int blk = blockIdx.x;
    const int d = blk >> 6, b = blk & 63;
    const int tid = threadIdx.x;
    const int g = tid >> 5;
    const int hh = tid & 31;
    float* hout = outsel ? g_h1 : g_h0;
    const float* whh = d ? whh_r : whh_f;

    U64 wp[16];
    {
        const ulonglong2* wr2 = (const ulonglong2*)(whh + (g * 32 + hh) * 32);
        #pragma unroll
        for (int r = 0; r < 8; r++){ ulonglong2 v = wr2[r]; wp[2*r] = v.x; wp[2*r+1] = v.y; }
    }

    __shared__ __align__(16) float hs[32];
    __shared__ __align__(16) float gbuf[96];
    if (tid < 32) hs[tid] = 0.0f;
    float c = 0.0f;
    __syncthreads();

    const float* xq = g_xp + (size_t)(d * 64 + b) * 1024 * 128 + g * 32 + hh;
    float cur = xq[0];
    float nxt = xq[128];

    float* outp = hout + (size_t)b * 1024 * 64 + d * 32 + hh;

    for (int s = 0; s < 1024; s++){
        float nn = 0.0f;
        if (s + 2 < 1024) nn = xq[(size_t)(s + 2) * 128];

        U64 a0 = 0ull, a1 = 0ull;
        const ulonglong2* h2 = (const ulonglong2*)hs;
        #pragma unroll
        for (int r = 0; r < 8; r++){
            ulonglong2 hv = h2[r];
            ffma2(a0, hv.x, wp[2*r]);
            ffma2(a1, hv.y, wp[2*r+1]);
        }
        float pre = cur + sum2(add2(a0, a1));
        float act = (g == 2) ? tanhx(pre) : sigf(pre);
        if (g < 3) gbuf[g * 32 + hh] = act;
        __syncthreads();

        if (g == 3){
            float iv = gbuf[hh];
            float fv = gbuf[32 + hh];
            float gv = gbuf[64 + hh];
            c = fmaf(fv, c, iv * gv);
            float hval = act * tanhx(c);
            hs[hh] = hval;
            int tout = d ? (1023 - s) : s;
            outp[(size_t)tout * 64] = hval;
        }
        __syncthreads();

        cur = nxt; nxt = nn;
    }
}

// ---------------- f32x2 GEMM w/ split-K + register double-buffer prefetch ----------------
__global__ void __launch_bounds__(256) fc_kernel(
    const float* __restrict__ W, int sel, int N, int K, int kPerSplit)
{
    const float* __restrict__ X = sel ? g_hidden : g_h1;
    float* __restrict__ part = sel ? g_part2 : g_part1;

    __shared__ float ws[32 * TW];
    __shared__ float fs[32 * TW];

    const int tid = threadIdx.x;
    const int nq = tid & 15;
    const int bq = tid >> 4;
    const int mbase = blockIdx.x * 128;
    const int kstart = blockIdx.y * kPerSplit;

    const int sn  = tid & 127, skq = tid >> 7;
    const int xb_ = tid & 63,  xkq = tid >> 6;

    const float* wptr = W + (size_t)(mbase + sn) * K + kstart + skq * 16;
    const float* xptr = X + (size_t)xb_ * K + kstart + xkq * 8;

    U64 acc[4][4];
    #pragma unroll
    for (int i = 0; i < 4; i++)
        #pragma unroll
        for (int j = 0; j < 4; j++) acc[i][j] = 0ull;

    // prefetch chunk 0 into registers
    float4 w0r, w1r, w2r, w3r, x0r, x1r;
    {
        const float4* srcw = (const float4*)wptr;
        w0r = srcw[0]; w1r = srcw[1]; w2r = srcw[2]; w3r = srcw[3];
        const float4* srcx = (const float4*)xptr;
        x0r = srcx[0]; x1r = srcx[1];
    }

    const int nchunk = kPerSplit / 32;
    for (int ch = 0; ch < nchunk; ch++){
        // regs -> smem
        {
            int kb = skq * 16;
            ws[(kb+ 0)*TW + sn] = w0r.x; ws[(kb+ 1)*TW + sn] = w0r.y;
            ws[(kb+ 2)*TW + sn] = w0r.z; ws[(kb+ 3)*TW + sn] = w0r.w;
            ws[(kb+ 4)*TW + sn] = w1r.x; ws[(kb+ 5)*TW + sn] = w1r.y;
            ws[(kb+ 6)*TW + sn] = w1r.z; ws[(kb+ 7)*TW + sn] = w1r.w;
            ws[(kb+ 8)*TW + sn] = w2r.x; ws[(kb+ 9)*TW + sn] = w2r.y;
            ws[(kb+10)*TW + sn] = w2r.z; ws[(kb+11)*TW + sn] = w2r.w;
            ws[(kb+12)*TW + sn] = w3r.x; ws[(kb+13)*TW + sn] = w3r.y;
            ws[(kb+14)*TW + sn] = w3r.z; ws[(kb+15)*TW + sn] = w3r.w;
            int xkb = xkq * 8;
            *(float2*)&fs[(xkb+0)*TW + 2*xb_] = make_float2(x0r.x, x0r.x);
            *(float2*)&fs[(xkb+1)*TW + 2*xb_] = make_float2(x0r.y, x0r.y);
            *(float2*)&fs[(xkb+2)*TW + 2*xb_] = make_float2(x0r.z, x0r.z);
            *(float2*)&fs[(xkb+3)*TW + 2*xb_] = make_float2(x0r.w, x0r.w);
            *(float2*)&fs[(xkb+4)*TW + 2*xb_] = make_float2(x1r.x, x1r.x);
            *(float2*)&fs[(xkb+5)*TW + 2*xb_] = make_float2(x1r.y, x1r.y);
            *(float2*)&fs[(xkb+6)*TW + 2*xb_] = make_float2(x1r.z, x1r.z);
            *(float2*)&fs[(xkb+7)*TW + 2*xb_] = make_float2(x1r.w, x1r.w);
        }
        __syncthreads();
        // issue next chunk's global loads (in flight during compute)
        if (ch + 1 < nchunk){
            const float4* srcw = (const float4*)(wptr + (ch + 1) * 32);
            w0r = srcw[0]; w1r = srcw[1]; w2r = srcw[2]; w3r = srcw[3];
            const float4* srcx = (const float4*)(xptr + (ch + 1) * 32);
            x0r = srcx[0]; x1r = srcx[1];
        }
        #pragma unroll
        for (int kk = 0; kk < 32; kk++){
            ulonglong2 wa = *(const ulonglong2*)&ws[kk*TW + nq*4];
            ulonglong2 wb = *(const ulonglong2*)&ws[kk*TW + 64 + nq*4];
            ulonglong2 xa = *(const ulonglong2*)&fs[kk*TW + bq*8];
            ulonglong2 xc = *(const ulonglong2*)&fs[kk*TW + bq*8 + 4];
            U64 xv0 = xa.x, xv1 = xa.y, xv2 = xc.x, xv3 = xc.y;
            ffma2(acc[0][0], xv0, wa.x); ffma2(acc[0][1], xv0, wa.y);
            ffma2(acc[0][2], xv0, wb.x); ffma2(acc[0][3], xv0, wb.y);
            ffma2(acc[1][0], xv1, wa.x); ffma2(acc[1][1], xv1, wa.y);
            ffma2(acc[1][2], xv1, wb.x); ffma2(acc[1][3], xv1, wb.y);
            ffma2(acc[2][0], xv2, wa.x); ffma2(acc[2][1], xv2, wa.y);
            ffma2(acc[2][2], xv2, wb.x); ffma2(acc[2][3], xv2, wb.y);
            ffma2(acc[3][0], xv3, wa.x); ffma2(acc[3][1], xv3, wa.y);
            ffma2(acc[3][2], xv3, wb.x); ffma2(acc[3][3], xv3, wb.y);
        }
        __syncthreads();
    }

    #pragma unroll
    for (int b4 = 0; b4 < 4; b4++){
        int b = bq * 4 + b4;
        float* dst = part + ((size_t)blockIdx.y * 64 + b) * N + mbase;
        *(float2*)(dst + nq*4)          = unpk(acc[b4][0]);
        *(float2*)(dst + nq*4 + 2)      = unpk(acc[b4][1]);
        *(float2*)(dst + 64 + nq*4)     = unpk(acc[b4][2]);
        *(float2*)(dst + 64 + nq*4 + 2) = unpk(acc[b4][3]);
    }
}

// ---------------- split-K reductions ----------------
__global__ void reduce1_kernel(const float* __restrict__ bias){
    int i = blockIdx.x * 256 + threadIdx.x;
    int m = i & 2047, b = i >> 11;
    float acc = bias[m];
    #pragma unroll
    for (int s = 0; s < 32; s++) acc += g_part1[((size_t)s * 64 + b) * 2048 + m];
    g_hidden[i] = fmaxf(acc, 0.0f);
}

__global__ void reduce2_kernel(const float* __restrict__ bias, float* __restrict__ out){
    int i = blockIdx.x * 256 + threadIdx.x;
    int n = i % 9216, b = i / 9216;
    float acc = bias[n];
    #pragma unroll
    for (int s = 0; s < 4; s++) acc += g_part2[((size_t)s * 64 + b) * 9216 + n];
    out[i] = acc;
}

// ---------------- launcher ----------------
extern "C" void kernel_launch(void* const* d_in, const int* in_sizes, int n_in,
                              void* d_out, int out_size)
{
    const float* x     = (const float*)d_in[0];
    const float* wih0  = (const float*)d_in[1];
    const float* whh0  = (const float*)d_in[2];
    const float* bih0  = (const float*)d_in[3];
    const float* bhh0  = (const float*)d_in[4];
    const float* wih0r = (const float*)d_in[5];
    const float* whh0r = (const float*)d_in[6];
    const float* bih0r = (const float*)d_in[7];
    const float* bhh0r = (const float*)d_in[8];
    const float* wih1  = (const float*)d_in[9];
    const float* whh1  = (const float*)d_in[10];
    const float* bih1  = (const float*)d_in[11];
    const float* bhh1  = (const float*)d_in[12];
    const float* wih1r = (const float*)d_in[13];
    const float* whh1r = (const float*)d_in[14];
    const float* bih1r = (const float*)d_in[15];
    const float* bhh1r = (const float*)d_in[16];
    const float* fc1w  = (const float*)d_in[17];
    const float* fc1b  = (const float*)d_in[18];
    const float* fc2w  = (const float*)d_in[19];
    const float* fc2b  = (const float*)d_in[20];
    float* out = (float*)d_out;

    xproj0_kernel<<<dim3(16, 64, 2), 256>>>(x, wih0, bih0, bhh0, wih0r, bih0r, bhh0r);
    lstm_kernel<<<128, 128>>>(whh0, whh0r, 0);
    xproj1_kernel<<<dim3(16, 64, 2), 256>>>(wih1, bih1, bhh1, wih1r, bih1r, bhh1r);
    lstm_kernel<<<128, 128>>>(whh1, whh1r, 1);

    // fc1: N=2048, K=65536, split-K=32 -> grid (16, 32)
    fc_kernel<<<dim3(16, 32), 256>>>(fc1w, 0, 2048, 65536, 2048);
    reduce1_kernel<<<512, 256>>>(fc1b);

    // fc2: N=9216, K=2048, split-K=4 -> grid (72, 4)
    fc_kernel<<<dim3(72, 4), 256>>>(fc2w, 1, 9216, 2048, 512);
    reduce2_kernel<<<2304, 256>>>(fc2b, out);
}

// round 7
// speedup vs baseline: 1.8802x; 1.0436x over previous
#include <cuda_runtime.h>

typedef unsigned long long U64;

// ---------------- static device scratch ----------------
__device__ float g_xp[16777216];   // [2][64][1024][128] gate pre-activations
__device__ float g_h0[4194304];    // [64][1024][64]
__device__ float g_h1[4194304];    // [64][1024][64]
__device__ float g_part1[8388608]; // [64][64][2048] fc1 split-K partials
__device__ float g_hidden[131072]; // [64][2048]
__device__ float g_part2[2359296]; // [4][64][9216] fc2 split-K partials

// ---------------- helpers ----------------
__device__ __forceinline__ void ffma2(U64 &acc, U64 a, U64 b){
    asm("fma.rn.f32x2 %0, %1, %2, %0;" : "+l"(acc) : "l"(a), "l"(b));
}
__device__ __forceinline__ U64 add2(U64 a, U64 b){
    U64 r; asm("add.rn.f32x2 %0, %1, %2;" : "=l"(r) : "l"(a), "l"(b)); return r;
}
__device__ __forceinline__ float2 unpk(U64 v){
    float2 r; asm("mov.b64 {%0, %1}, %2;" : "=f"(r.x), "=f"(r.y) : "l"(v)); return r;
}
__device__ __forceinline__ float sum2(U64 v){ float2 r = unpk(v); return r.x + r.y; }
__device__ __forceinline__ float fex2(float x){ float r; asm("ex2.approx.ftz.f32 %0, %1;" : "=f"(r) : "f"(x)); return r; }
__device__ __forceinline__ float frcp(float x){ float r; asm("rcp.approx.ftz.f32 %0, %1;" : "=f"(r) : "f"(x)); return r; }
__device__ __forceinline__ float sigf (float x){ return frcp(1.0f + fex2(-1.4426950408889634f * x)); }
__device__ __forceinline__ float tanhx(float x){ return fmaf(-2.0f, frcp(1.0f + fex2(2.8853900817779268f * x)), 1.0f); }

#define TW 132   // padded smem row stride (floats)

// ---------------- xproj layer 0: tiled, K=9 ----------------
__global__ void __launch_bounds__(256) xproj0_kernel(const float* __restrict__ x,
    const float* __restrict__ wf, const float* __restrict__ bif, const float* __restrict__ bhf,
    const float* __restrict__ wr, const float* __restrict__ bir, const float* __restrict__ bhr)
{
    __shared__ float ws[9 * TW];
    __shared__ float fs[9 * TW];
    const int tid = threadIdx.x;
    const int s0 = blockIdx.x * 64;
    const int b  = blockIdx.y;
    const int d  = blockIdx.z;
    const float* w  = d ? wr : wf;
    const float* bi = d ? bir : bif;
    const float* bh = d ? bhr : bhf;

    if (tid < 128){
        const float* src = w + tid * 9;
        #pragma unroll
        for (int k = 0; k < 9; k++) ws[k * TW + tid] = src[k];
    } else if (tid < 192){
        int r = tid - 128;
        int s = s0 + r;
        int tsrc = d ? (1023 - s) : s;
        const float* src = x + ((size_t)b * 1024 + tsrc) * 9;
        #pragma unroll
        for (int k = 0; k < 9; k++){
            float v = src[k];
            *(float2*)&fs[k * TW + 2 * r] = make_float2(v, v);
        }
    }
    __syncthreads();

    const int nq = tid & 15;
    const int bq = tid >> 4;
    U64 acc[4][4];
    #pragma unroll
    for (int i = 0; i < 4; i++)
        #pragma unroll
        for (int j = 0; j < 4; j++) acc[i][j] = 0ull;

    #pragma unroll
    for (int kk = 0; kk < 9; kk++){
        ulonglong2 wa = *(const ulonglong2*)&ws[kk*TW + nq*4];
        ulonglong2 wb = *(const ulonglong2*)&ws[kk*TW + 64 + nq*4];
        ulonglong2 xa = *(const ulonglong2*)&fs[kk*TW + bq*8];
        ulonglong2 xc = *(const ulonglong2*)&fs[kk*TW + bq*8 + 4];
        U64 xv0 = xa.x, xv1 = xa.y, xv2 = xc.x, xv3 = xc.y;
        ffma2(acc[0][0], xv0, wa.x); ffma2(acc[0][1], xv0, wa.y);
        ffma2(acc[0][2], xv0, wb.x); ffma2(acc[0][3], xv0, wb.y);
        ffma2(acc[1][0], xv1, wa.x); ffma2(acc[1][1], xv1, wa.y);
        ffma2(acc[1][2], xv1, wb.x); ffma2(acc[1][3], xv1, wb.y);
        ffma2(acc[2][0], xv2, wa.x); ffma2(acc[2][1], xv2, wa.y);
        ffma2(acc[2][2], xv2, wb.x); ffma2(acc[2][3], xv2, wb.y);
        ffma2(acc[3][0], xv3, wa.x); ffma2(acc[3][1], xv3, wa.y);
        ffma2(acc[3][2], xv3, wb.x); ffma2(acc[3][3], xv3, wb.y);
    }

    int j0 = nq * 4, j1 = 64 + nq * 4;
    float bv[8];
    #pragma unroll
    for (int q = 0; q < 4; q++){ bv[q] = bi[j0+q] + bh[j0+q]; bv[4+q] = bi[j1+q] + bh[j1+q]; }

    float* base = g_xp + ((size_t)(d * 64 + b) * 1024 + s0) * 128;
    #pragma unroll
    for (int b4 = 0; b4 < 4; b4++){
        float* dst = base + (size_t)(bq * 4 + b4) * 128;
        float2 v0 = unpk(acc[b4][0]); v0.x += bv[0]; v0.y += bv[1];
        float2 v1 = unpk(acc[b4][1]); v1.x += bv[2]; v1.y += bv[3];
        float2 v2 = unpk(acc[b4][2]); v2.x += bv[4]; v2.y += bv[5];
        float2 v3 = unpk(acc[b4][3]); v3.x += bv[6]; v3.y += bv[7];
        *(float2*)(dst + j0)     = v0;
        *(float2*)(dst + j0 + 2) = v1;
        *(float2*)(dst + j1)     = v2;
        *(float2*)(dst + j1 + 2) = v3;
    }
}

// ---------------- xproj layer 1: tiled GEMM, K=64 ----------------
__global__ void __launch_bounds__(256) xproj1_kernel(
    const float* __restrict__ wf, const float* __restrict__ bif, const float* __restrict__ bhf,
    const float* __restrict__ wr, const float* __restrict__ bir, const float* __restrict__ bhr)
{
    __shared__ float ws[32 * TW];
    __shared__ float fs[32 * TW];
    const int tid = threadIdx.x;
    const int s0 = blockIdx.x * 64;
    const int b  = blockIdx.y;
    const int d  = blockIdx.z;
    const float* w  = d ? wr : wf;
    const float* bi = d ? bir : bif;
    const float* bh = d ? bhr : bhf;

    const int sn  = tid & 127, skq = tid >> 7;
    const int xr  = tid & 63,  xkq = tid >> 6;
    int s = s0 + xr;
    int tsrc = d ? (1023 - s) : s;
    const float* wptr = w + sn * 64 + skq * 16;
    const float* hptr = g_h0 + ((size_t)b * 1024 + tsrc) * 64 + xkq * 8;

    const int nq = tid & 15;
    const int bq = tid >> 4;
    U64 acc[4][4];
    #pragma unroll
    for (int i = 0; i < 4; i++)
        #pragma unroll
        for (int j = 0; j < 4; j++) acc[i][j] = 0ull;

    #pragma unroll
    for (int ch = 0; ch < 2; ch++){
        if (ch){ __syncthreads(); }
        {
            const float4* src = (const float4*)(wptr + ch * 32);
            float4 v0 = src[0], v1 = src[1], v2 = src[2], v3 = src[3];
            int kb = skq * 16;
            ws[(kb+ 0)*TW + sn] = v0.x; ws[(kb+ 1)*TW + sn] = v0.y;
            ws[(kb+ 2)*TW + sn] = v0.z; ws[(kb+ 3)*TW + sn] = v0.w;
            ws[(kb+ 4)*TW + sn] = v1.x; ws[(kb+ 5)*TW + sn] = v1.y;
            ws[(kb+ 6)*TW + sn] = v1.z; ws[(kb+ 7)*TW + sn] = v1.w;
            ws[(kb+ 8)*TW + sn] = v2.x; ws[(kb+ 9)*TW + sn] = v2.y;
            ws[(kb+10)*TW + sn] = v2.z; ws[(kb+11)*TW + sn] = v2.w;
            ws[(kb+12)*TW + sn] = v3.x; ws[(kb+13)*TW + sn] = v3.y;
            ws[(kb+14)*TW + sn] = v3.z; ws[(kb+15)*TW + sn] = v3.w;
        }
        {
            const float4* src = (const float4*)(hptr + ch * 32);
            float4 u0 = src[0], u1 = src[1];
            int kb = xkq * 8;
            *(float2*)&fs[(kb+0)*TW + 2*xr] = make_float2(u0.x, u0.x);
            *(float2*)&fs[(kb+1)*TW + 2*xr] = make_float2(u0.y, u0.y);
            *(float2*)&fs[(kb+2)*TW + 2*xr] = make_float2(u0.z, u0.z);
            *(float2*)&fs[(kb+3)*TW + 2*xr] = make_float2(u0.w, u0.w);
            *(float2*)&fs[(kb+4)*TW + 2*xr] = make_float2(u1.x, u1.x);
            *(float2*)&fs[(kb+5)*TW + 2*xr] = make_float2(u1.y, u1.y);
            *(float2*)&fs[(kb+6)*TW + 2*xr] = make_float2(u1.z, u1.z);
            *(float2*)&fs[(kb+7)*TW + 2*xr] = make_float2(u1.w, u1.w);
        }
        __syncthreads();
        #pragma unroll
        for (int kk = 0; kk < 32; kk++){
            ulonglong2 wa = *(const ulonglong2*)&ws[kk*TW + nq*4];
            ulonglong2 wb = *(const ulonglong2*)&ws[kk*TW + 64 + nq*4];
            ulonglong2 xa = *(const ulonglong2*)&fs[kk*TW + bq*8];
            ulonglong2 xc = *(const ulonglong2*)&fs[kk*TW + bq*8 + 4];
            U64 xv0 = xa.x, xv1 = xa.y, xv2 = xc.x, xv3 = xc.y;
            ffma2(acc[0][0], xv0, wa.x); ffma2(acc[0][1], xv0, wa.y);
            ffma2(acc[0][2], xv0, wb.x); ffma2(acc[0][3], xv0, wb.y);
            ffma2(acc[1][0], xv1, wa.x); ffma2(acc[1][1], xv1, wa.y);
            ffma2(acc[1][2], xv1, wb.x); ffma2(acc[1][3], xv1, wb.y);
            ffma2(acc[2][0], xv2, wa.x); ffma2(acc[2][1], xv2, wa.y);
            ffma2(acc[2][2], xv2, wb.x); ffma2(acc[2][3], xv2, wb.y);
            ffma2(acc[3][0], xv3, wa.x); ffma2(acc[3][1], xv3, wa.y);
            ffma2(acc[3][2], xv3, wb.x); ffma2(acc[3][3], xv3, wb.y);
        }
    }

    int j0 = nq * 4, j1 = 64 + nq * 4;
    float bv[8];
    #pragma unroll
    for (int q = 0; q < 4; q++){ bv[q] = bi[j0+q] + bh[j0+q]; bv[4+q] = bi[j1+q] + bh[j1+q]; }

    float* base = g_xp + ((size_t)(d * 64 + b) * 1024 + s0) * 128;
    #pragma unroll
    for (int b4 = 0; b4 < 4; b4++){
        float* dst = base + (size_t)(bq * 4 + b4) * 128;
        float2 v0 = unpk(acc[b4][0]); v0.x += bv[0]; v0.y += bv[1];
        float2 v1 = unpk(acc[b4][1]); v1.x += bv[2]; v1.y += bv[3];
        float2 v2 = unpk(acc[b4][2]); v2.x += bv[4]; v2.y += bv[5];
        float2 v3 = unpk(acc[b4][3]); v3.x += bv[6]; v3.y += bv[7];
        *(float2*)(dst + j0)     = v0;
        *(float2*)(dst + j0 + 2) = v1;
        *(float2*)(dst + j1)     = v2;
        *(float2*)(dst + j1 + 2) = v3;
    }
}

// ---------------- LSTM: 4 warps/(dir,batch), ONE barrier/step, redundant c/h ----------------
__global__ void __launch_bounds__(128, 1) lstm_kernel(
    const float* __restrict__ whh_f, const float* __restrict__ whh_r, int outsel)
{
    const int blk = blockIdx.x;
    const int d = blk >> 6, b = blk & 63;
    const int tid = threadIdx.x;
    const int g = tid >> 5;              // this warp's gate (i,f,g,o)
    const int hh = tid & 31;
    float* hout = outsel ? g_h1 : g_h0;
    const float* whh = d ? whh_r : whh_f;

    U64 wp[16];
    {
        const ulonglong2* wr2 = (const ulonglong2*)(whh + (g * 32 + hh) * 32);
        #pragma unroll
        for (int r = 0; r < 8; r++){ ulonglong2 v = wr2[r]; wp[2*r] = v.x; wp[2*r+1] = v.y; }
    }

    __shared__ __align__(16) float hs[32];
    __shared__ __align__(16) float gbuf[2][128];  // double-buffered gate exchange
    if (tid < 32) hs[tid] = 0.0f;
    float c = 0.0f;                               // replicated per-lane across all warps
    __syncthreads();

    const float* xq = g_xp + (size_t)(d * 64 + b) * 1024 * 128 + g * 32 + hh;
    float cur = xq[0];
    float nxt = xq[128];

    float* outp = hout + (size_t)b * 1024 * 64 + d * 32 + hh;

    for (int s = 0; s < 1024; s++){
        float nn = 0.0f;
        if (s + 2 < 1024) nn = xq[(size_t)(s + 2) * 128];

        // gate pre-activation from hs (own-warp writes ordered by syncwarp below)
        U64 a0 = 0ull, a1 = 0ull;
        const ulonglong2* h2 = (const ulonglong2*)hs;
        #pragma unroll
        for (int r = 0; r < 8; r++){
            ulonglong2 hv = h2[r];
            ffma2(a0, hv.x, wp[2*r]);
            ffma2(a1, hv.y, wp[2*r+1]);
        }
        float pre = cur + sum2(add2(a0, a1));
        float act = (g == 2) ? tanhx(pre) : sigf(pre);
        float* gb = gbuf[s & 1];
        gb[g * 32 + hh] = act;
        __syncthreads();                     // the ONLY block barrier per step

        float iv = gb[hh];
        float fv = gb[32 + hh];
        float gv = gb[64 + hh];
        float ov = gb[96 + hh];
        c = fmaf(fv, c, iv * gv);            // identical in every warp
        float hval = ov * tanhx(c);
        hs[hh] = hval;                       // all warps write identical value
        __syncwarp();                        // order own writes before next dot
        if (g == 0){
            int tout = d ? (1023 - s) : s;
            outp[(size_t)tout * 64] = hval;
        }
        cur = nxt; nxt = nn;
    }
}

// ---------------- f32x2 GEMM, split-K, double-buffered smem (1 sync/chunk) ----------------
// chunk K=16; buffers 2 x (16 x TW) x 2 arrays = 33.8KB static
__global__ void __launch_bounds__(256) fc_kernel(
    const float* __restrict__ W, int sel, int N, int K, int kPerSplit)
{
    const float* __restrict__ X = sel ? g_hidden : g_h1;
    float* __restrict__ part = sel ? g_part2 : g_part1;

    __shared__ float ws[2][16 * TW];
    __shared__ float fs[2][16 * TW];

    const int tid = threadIdx.x;
    const int nq = tid & 15;
    const int bq = tid >> 4;
    const int mbase = blockIdx.x * 128;
    const int kstart = blockIdx.y * kPerSplit;

    const int sn  = tid & 127, skq = tid >> 7;   // W: row sn, k-offset skq*8
    const int xr  = tid & 63,  xkq = tid >> 6;   // X: row xr, k-offset xkq*4

    const float* wptr = W + (size_t)(mbase + sn) * K + kstart + skq * 8;
    const float* xptr = X + (size_t)xr * K + kstart + xkq * 4;

    U64 acc[4][4];
    #pragma unroll
    for (int i = 0; i < 4; i++)
        #pragma unroll
        for (int j = 0; j < 4; j++) acc[i][j] = 0ull;

    // prefetch chunk 0
    float4 wA, wB, xA;
    {
        const float4* sw = (const float4*)wptr;
        wA = sw[0]; wB = sw[1];
        xA = *(const float4*)xptr;
    }

    const int nchunk = kPerSplit / 16;
    for (int ch = 0; ch < nchunk; ch++){
        int buf = ch & 1;
        {   // stage current regs -> smem buf
            float* wsb = ws[buf];
            int kb = skq * 8;
            wsb[(kb+0)*TW + sn] = wA.x; wsb[(kb+1)*TW + sn] = wA.y;
            wsb[(kb+2)*TW + sn] = wA.z; wsb[(kb+3)*TW + sn] = wA.w;
            wsb[(kb+4)*TW + sn] = wB.x; wsb[(kb+5)*TW + sn] = wB.y;
            wsb[(kb+6)*TW + sn] = wB.z; wsb[(kb+7)*TW + sn] = wB.w;
            float* fsb = fs[buf];
            int xkb = xkq * 4;
            *(float2*)&fsb[(xkb+0)*TW + 2*xr] = make_float2(xA.x, xA.x);
            *(float2*)&fsb[(xkb+1)*TW + 2*xr] = make_float2(xA.y, xA.y);
            *(float2*)&fsb[(xkb+2)*TW + 2*xr] = make_float2(xA.z, xA.z);
            *(float2*)&fsb[(xkb+3)*TW + 2*xr] = make_float2(xA.w, xA.w);
        }
        __syncthreads();
        if (ch + 1 < nchunk){   // global prefetch for next chunk (in flight over compute)
            const float4* sw = (const float4*)(wptr + (ch + 1) * 16);
            wA = sw[0]; wB = sw[1];
            xA = *(const float4*)(xptr + (ch + 1) * 16);
        }
        const float* wsb = ws[buf];
        const float* fsb = fs[buf];
        #pragma unroll
        for (int kk = 0; kk < 16; kk++){
            ulonglong2 wa = *(const ulonglong2*)&wsb[kk*TW + nq*4];
            ulonglong2 wb = *(const ulonglong2*)&wsb[kk*TW + 64 + nq*4];
            ulonglong2 xa = *(const ulonglong2*)&fsb[kk*TW + bq*8];
            ulonglong2 xc = *(const ulonglong2*)&fsb[kk*TW + bq*8 + 4];
            U64 xv0 = xa.x, xv1 = xa.y, xv2 = xc.x, xv3 = xc.y;
            ffma2(acc[0][0], xv0, wa.x); ffma2(acc[0][1], xv0, wa.y);
            ffma2(acc[0][2], xv0, wb.x); ffma2(acc[0][3], xv0, wb.y);
            ffma2(acc[1][0], xv1, wa.x); ffma2(acc[1][1], xv1, wa.y);
            ffma2(acc[1][2], xv1, wb.x); ffma2(acc[1][3], xv1, wb.y);
            ffma2(acc[2][0], xv2, wa.x); ffma2(acc[2][1], xv2, wa.y);
            ffma2(acc[2][2], xv2, wb.x); ffma2(acc[2][3], xv2, wb.y);
            ffma2(acc[3][0], xv3, wa.x); ffma2(acc[3][1], xv3, wa.y);
            ffma2(acc[3][2], xv3, wb.x); ffma2(acc[3][3], xv3, wb.y);
        }
    }

    #pragma unroll
    for (int b4 = 0; b4 < 4; b4++){
        int b = bq * 4 + b4;
        float* dst = part + ((size_t)blockIdx.y * 64 + b) * N + mbase;
        *(float2*)(dst + nq*4)          = unpk(acc[b4][0]);
        *(float2*)(dst + nq*4 + 2)      = unpk(acc[b4][1]);
        *(float2*)(dst + 64 + nq*4)     = unpk(acc[b4][2]);
        *(float2*)(dst + 64 + nq*4 + 2) = unpk(acc[b4][3]);
    }
}

// ---------------- split-K reductions ----------------
__global__ void reduce1_kernel(const float* __restrict__ bias){
    int i = blockIdx.x * 256 + threadIdx.x;   // 131072
    int m = i & 2047, b = i >> 11;
    float acc = bias[m];
    #pragma unroll
    for (int s = 0; s < 64; s++) acc += g_part1[((size_t)s * 64 + b) * 2048 + m];
    g_hidden[i] = fmaxf(acc, 0.0f);
}

__global__ void reduce2_kernel(const float* __restrict__ bias, float* __restrict__ out){
    int i = blockIdx.x * 256 + threadIdx.x;   // 589824
    int n = i % 9216, b = i / 9216;
    float acc = bias[n];
    #pragma unroll
    for (int s = 0; s < 4; s++) acc += g_part2[((size_t)s * 64 + b) * 9216 + n];
    out[i] = acc;
}

// ---------------- launcher ----------------
extern "C" void kernel_launch(void* const* d_in, const int* in_sizes, int n_in,
                              void* d_out, int out_size)
{
    const float* x     = (const float*)d_in[0];
    const float* wih0  = (const float*)d_in[1];
    const float* whh0  = (const float*)d_in[2];
    const float* bih0  = (const float*)d_in[3];
    const float* bhh0  = (const float*)d_in[4];
    const float* wih0r = (const float*)d_in[5];
    const float* whh0r = (const float*)d_in[6];
    const float* bih0r = (const float*)d_in[7];
    const float* bhh0r = (const float*)d_in[8];
    const float* wih1  = (const float*)d_in[9];
    const float* whh1  = (const float*)d_in[10];
    const float* bih1  = (const float*)d_in[11];
    const float* bhh1  = (const float*)d_in[12];
    const float* wih1r = (const float*)d_in[13];
    const float* whh1r = (const float*)d_in[14];
    const float* bih1r = (const float*)d_in[15];
    const float* bhh1r = (const float*)d_in[16];
    const float* fc1w  = (const float*)d_in[17];
    const float* fc1b  = (const float*)d_in[18];
    const float* fc2w  = (const float*)d_in[19];
    const float* fc2b  = (const float*)d_in[20];
    float* out = (float*)d_out;

    xproj0_kernel<<<dim3(16, 64, 2), 256>>>(x, wih0, bih0, bhh0, wih0r, bih0r, bhh0r);
    lstm_kernel<<<128, 128>>>(whh0, whh0r, 0);
    xproj1_kernel<<<dim3(16, 64, 2), 256>>>(wih1, bih1, bhh1, wih1r, bih1r, bhh1r);
    lstm_kernel<<<128, 128>>>(whh1, whh1r, 1);

    // fc1: N=2048, K=65536, split-K=64 (kPerSplit=1024) -> grid (16, 64)
    fc_kernel<<<dim3(16, 64), 256>>>(fc1w, 0, 2048, 65536, 1024);
    reduce1_kernel<<<512, 256>>>(fc1b);

    // fc2: N=9216, K=2048, split-K=4 (kPerSplit=512) -> grid (72, 4)
    fc_kernel<<<dim3(72, 4), 256>>>(fc2w, 1, 9216, 2048, 512);
    reduce2_kernel<<<2304, 256>>>(fc2b, out);
}